// round 12
// baseline (speedup 1.0000x reference)
#include <cuda_runtime.h>
#include <math.h>

#define NM 1024
#define H 256
#define W 256
#define HW (H * W)
#define TOTAL ((size_t)NM * HW)
#define CHUNKS 4
#define NPART (NM * CHUNKS)

#define PRED_IOU_THRESH 0.88f
#define STABILITY_THRESH 0.95f
#define BOX_NMS_THRESH 0.7f

// Per-mask / per-partial scratch (allocation-free: __device__ globals)
__device__ int4   g_pA[NPART];   // hi, lo, minr, maxr
__device__ int2   g_pB[NPART];   // minc, maxc
__device__ float4 g_boxes[NM];   // xyxy inclusive, zeros if empty
__device__ float  g_gated[NM];   // iou_pred if kept else 0

// ---------------------------------------------------------------------------
// Side stream: zero-fill output regions of masks that fail the iou_pred
// threshold (invalid regardless of stats/NMS). Independent of stats, so it
// runs CONCURRENTLY with the stats read pass, overlapping write & read BW.
// ---------------------------------------------------------------------------
__global__ void __launch_bounds__(256) zfill_kernel(const float* __restrict__ iou_preds,
                                                    float* __restrict__ dout) {
    const int m = blockIdx.y;
    if (iou_preds[m] > PRED_IOU_THRESH) return;   // handled post-NMS
    const size_t base4 = (size_t)m * (HW / 4) + blockIdx.x * 2048;
    float4* o = reinterpret_cast<float4*>(dout) + base4;
    const float4 z = make_float4(0.f, 0.f, 0.f, 0.f);
#pragma unroll
    for (int it = 0; it < 8; ++it)
        __stcs(&o[it * 256 + threadIdx.x], z);
}

// ---------------------------------------------------------------------------
// Pass 1: partial stats, READ-ONLY. 4 blocks per mask (64 rows each),
// 256 threads, 16 float4 per thread, streaming loads.
// ---------------------------------------------------------------------------
__global__ void __launch_bounds__(256) stats_kernel(const float* __restrict__ logits) {
    const int blk = blockIdx.x;
    const int m = blk >> 2;
    const int chunk = blk & 3;
    const int tid = threadIdx.x;
    const float4* base = reinterpret_cast<const float4*>(logits)
                       + (size_t)m * (HW / 4) + chunk * 4096;

    int hi = 0, lo = 0;
    unsigned rowbits = 0;
    float cm0 = -1e30f, cm1 = -1e30f, cm2 = -1e30f, cm3 = -1e30f;

#pragma unroll
    for (int it = 0; it < 16; ++it) {
        float4 v = __ldcs(&base[it * 256 + tid]);
        hi += (v.x > 1.0f) + (v.y > 1.0f) + (v.z > 1.0f) + (v.w > 1.0f);
        lo += (v.x > -1.0f) + (v.y > -1.0f) + (v.z > -1.0f) + (v.w > -1.0f);
        cm0 = fmaxf(cm0, v.x);
        cm1 = fmaxf(cm1, v.y);
        cm2 = fmaxf(cm2, v.z);
        cm3 = fmaxf(cm3, v.w);
        float mx = fmaxf(fmaxf(v.x, v.y), fmaxf(v.z, v.w));
        if (mx > 0.0f) rowbits |= (1u << it);
    }

    const int col0 = (tid * 4) & 255;
    int minc = W, maxc = -1;
    if (cm0 > 0.0f) { minc = col0;                 maxc = col0;     }
    if (cm1 > 0.0f) { minc = min(minc, col0 + 1);  maxc = col0 + 1; }
    if (cm2 > 0.0f) { minc = min(minc, col0 + 2);  maxc = col0 + 2; }
    if (cm3 > 0.0f) { minc = min(minc, col0 + 3);  maxc = col0 + 3; }
    int minr = H, maxr = -1;
    if (rowbits) {
        int rb = chunk * 64 + (tid >> 6);
        minr = rb + 4 * (__ffs(rowbits) - 1);
        maxr = rb + 4 * (31 - __clz(rowbits));
    }

#pragma unroll
    for (int off = 16; off > 0; off >>= 1) {
        hi   += __shfl_down_sync(0xffffffffu, hi, off);
        lo   += __shfl_down_sync(0xffffffffu, lo, off);
        minr = min(minr, __shfl_down_sync(0xffffffffu, minr, off));
        maxr = max(maxr, __shfl_down_sync(0xffffffffu, maxr, off));
        minc = min(minc, __shfl_down_sync(0xffffffffu, minc, off));
        maxc = max(maxc, __shfl_down_sync(0xffffffffu, maxc, off));
    }

    __shared__ int sh[8][6];
    int warp = tid >> 5;
    if ((tid & 31) == 0) {
        sh[warp][0] = hi;  sh[warp][1] = lo;
        sh[warp][2] = minr; sh[warp][3] = maxr;
        sh[warp][4] = minc; sh[warp][5] = maxc;
    }
    __syncthreads();
    if (tid == 0) {
#pragma unroll
        for (int wq = 1; wq < 8; ++wq) {
            hi += sh[wq][0]; lo += sh[wq][1];
            minr = min(minr, sh[wq][2]); maxr = max(maxr, sh[wq][3]);
            minc = min(minc, sh[wq][4]); maxc = max(maxc, sh[wq][5]);
        }
        g_pA[blk] = make_int4(hi, lo, minr, maxr);
        g_pB[blk] = make_int2(minc, maxc);
    }
}

// ---------------------------------------------------------------------------
// IoU helper (exact match of reference, incl. 1e-6 clamp)
// ---------------------------------------------------------------------------
__device__ __forceinline__ float box_iou(float4 a, float4 b, float area_b) {
    float x0 = fmaxf(a.x, b.x);
    float y0 = fmaxf(a.y, b.y);
    float x1 = fminf(a.z, b.z);
    float y1 = fminf(a.w, b.w);
    float inter = fmaxf(x1 - x0, 0.0f) * fmaxf(y1 - y0, 0.0f);
    float area_a = fmaxf(a.z - a.x, 0.0f) * fmaxf(a.w - a.y, 0.0f);
    return inter / fmaxf(area_a + area_b - inter, 1e-6f);
}

// ---------------------------------------------------------------------------
// NMS: single block, 1024 threads. Merge partials -> validity/box.
// Fast path (V<=256): ballot compaction, 256-wide bitonic, adjacency bitmask
// + single-thread sweep. Fallback (V>256): exact full sort + greedy.
// ---------------------------------------------------------------------------
__global__ void __launch_bounds__(1024) nms_kernel(const float* __restrict__ iou_preds,
                                                   float* __restrict__ dout,
                                                   long long out_size) {
    __shared__ float    css[256];
    __shared__ int      cidx[256];
    __shared__ float4   cbox[256];
    __shared__ unsigned adj[256][8];
    __shared__ unsigned removed_sh[8];
    __shared__ int      woff[33];
    __shared__ unsigned char keep_orig[NM];

    const int t = threadIdx.x;
    const int lane = t & 31;
    const int warp = t >> 5;

    int hi = 0, lo = 0, minr = H, maxr = -1, minc = W, maxc = -1;
#pragma unroll
    for (int c = 0; c < CHUNKS; ++c) {
        int4 a = g_pA[t * CHUNKS + c];
        int2 b = g_pB[t * CHUNKS + c];
        hi += a.x; lo += a.y;
        minr = min(minr, a.z); maxr = max(maxr, a.w);
        minc = min(minc, b.x); maxc = max(maxc, b.y);
    }
    float stability = (float)hi / fmaxf((float)lo, 1.0f);
    float iou_p = iou_preds[t];
    bool valid = (iou_p > PRED_IOU_THRESH) && (stability >= STABILITY_THRESH);
    float4 box = (maxr < 0) ? make_float4(0.f, 0.f, 0.f, 0.f)
                            : make_float4((float)minc, (float)minr, (float)maxc, (float)maxr);
    g_boxes[t] = box;
    keep_orig[t] = 0;

    unsigned wmask = __ballot_sync(0xffffffffu, valid);
    if (lane == 0) woff[warp] = __popc(wmask);
    __syncthreads();
    if (t < 32) {
        int v = woff[t];
        int acc = v;
#pragma unroll
        for (int off = 1; off < 32; off <<= 1) {
            int n = __shfl_up_sync(0xffffffffu, acc, off);
            if (t >= off) acc += n;
        }
        woff[t] = acc - v;
        if (t == 31) woff[32] = acc;
    }
    __syncthreads();
    const int V = woff[32];
    if (valid && V <= 256) {
        int mypos = woff[warp] + __popc(wmask & ((1u << lane) - 1u));
        css[mypos] = iou_p;
        cidx[mypos] = t;
        cbox[mypos] = box;
    }

    if (V <= 256) {
        if (t >= V && t < 256) {
            css[t] = -INFINITY;
            cidx[t] = NM + t;
            cbox[t] = make_float4(0.f, 0.f, 0.f, 0.f);
        }
        reinterpret_cast<unsigned*>(adj)[t] = 0;
        reinterpret_cast<unsigned*>(adj)[t + 1024] = 0;
        __syncthreads();

        for (int k = 2; k <= 256; k <<= 1) {
            for (int j = k >> 1; j > 0; j >>= 1) {
                if (t < 256) {
                    int ixj = t ^ j;
                    if (ixj > t) {
                        float sa = css[t], sb_ = css[ixj];
                        int   ia = cidx[t], ib = cidx[ixj];
                        bool less = (sa > sb_) || (sa == sb_ && ia < ib);
                        bool dir = ((t & k) == 0);
                        if (less != dir) {
                            css[t] = sb_; css[ixj] = sa;
                            cidx[t] = ib; cidx[ixj] = ia;
                            float4 ba = cbox[t];
                            cbox[t] = cbox[ixj]; cbox[ixj] = ba;
                        }
                    }
                }
                __syncthreads();
            }
        }

        if (t < V) {
            float4 bt = cbox[t];
            float area_t = fmaxf(bt.z - bt.x, 0.0f) * fmaxf(bt.w - bt.y, 0.0f);
            for (int i = 0; i < t; ++i) {
                if (box_iou(cbox[i], bt, area_t) > BOX_NMS_THRESH)
                    atomicOr(&adj[i][t >> 5], 1u << (t & 31));
            }
        }
        __syncthreads();
        if (t == 0) {
            unsigned removed[8] = {0,0,0,0,0,0,0,0};
            int nw = (V + 31) >> 5;
            for (int i = 0; i < V; ++i) {
                if (!((removed[i >> 5] >> (i & 31)) & 1u)) {
                    for (int w = 0; w < nw; ++w) removed[w] |= adj[i][w];
                }
            }
#pragma unroll
            for (int w = 0; w < 8; ++w) removed_sh[w] = removed[w];
        }
        __syncthreads();
        if (t < V) {
            bool kept = !((removed_sh[t >> 5] >> (t & 31)) & 1u);
            if (kept) keep_orig[cidx[t]] = 1;
        }
        __syncthreads();
    } else {
        __shared__ float  ss[NM];
        __shared__ int    si[NM];
        __shared__ float4 sbx[NM];
        __shared__ int    sk[NM];
        ss[t] = valid ? iou_p : -INFINITY;
        si[t] = t;
        __syncthreads();
        for (int k = 2; k <= NM; k <<= 1) {
            for (int j = k >> 1; j > 0; j >>= 1) {
                int ixj = t ^ j;
                if (ixj > t) {
                    float sa = ss[t], sb_ = ss[ixj];
                    int   ia = si[t], ib = si[ixj];
                    bool less = (sa > sb_) || (sa == sb_ && ia < ib);
                    bool dir = ((t & k) == 0);
                    if (less != dir) {
                        ss[t] = sb_; ss[ixj] = sa;
                        si[t] = ib;  si[ixj] = ia;
                    }
                }
                __syncthreads();
            }
        }
        sbx[t] = g_boxes[si[t]];
        sk[t] = (ss[t] > -INFINITY) ? 1 : 0;
        __syncthreads();
        float4 bt = sbx[t];
        float area_t = fmaxf(bt.z - bt.x, 0.0f) * fmaxf(bt.w - bt.y, 0.0f);
        for (int i = 0; i < V; ++i) {
            if (sk[i]) {
                float iou = box_iou(sbx[i], bt, area_t);
                if (t > i && iou > BOX_NMS_THRESH) sk[t] = 0;
            }
            __syncthreads();
        }
        if (sk[t]) keep_orig[si[t]] = 1;
        __syncthreads();
    }

    int kept = keep_orig[t];
    g_gated[t] = kept ? iou_p : 0.0f;
    if (out_size >= (long long)(TOTAL + NM)) {
        dout[TOTAL + t] = kept ? 1.0f : 0.0f;
    }
    if (out_size >= (long long)(TOTAL + NM + 4 * NM)) {
        float4* boxout = reinterpret_cast<float4*>(dout + TOTAL + NM);
        boxout[t] = g_boxes[t];
    }
}

// ---------------------------------------------------------------------------
// Post-NMS output: only masks with iou_pred > thresh (rest zero-filled on the
// side stream). Suppressed -> zero-fill; kept -> sigmoid * g.
// ---------------------------------------------------------------------------
__global__ void __launch_bounds__(256) output_kernel(const float* __restrict__ logits,
                                                     const float* __restrict__ iou_preds,
                                                     float* __restrict__ dout) {
    const int m = blockIdx.y;
    if (iou_preds[m] <= PRED_IOU_THRESH) return;   // zero-filled on side stream

    const float g = g_gated[m];
    const size_t base4 = (size_t)m * (HW / 4) + blockIdx.x * 2048;
    float4* o = reinterpret_cast<float4*>(dout) + base4;

    if (g == 0.0f) {
        float4 z = make_float4(0.f, 0.f, 0.f, 0.f);
#pragma unroll
        for (int it = 0; it < 8; ++it)
            __stcs(&o[it * 256 + threadIdx.x], z);
    } else {
        const float4* in = reinterpret_cast<const float4*>(logits) + base4;
#pragma unroll
        for (int it = 0; it < 8; ++it) {
            float4 v = __ldcs(&in[it * 256 + threadIdx.x]);
            float4 r;
            r.x = g / (1.0f + __expf(-v.x));
            r.y = g / (1.0f + __expf(-v.y));
            r.z = g / (1.0f + __expf(-v.z));
            r.w = g / (1.0f + __expf(-v.w));
            __stcs(&o[it * 256 + threadIdx.x], r);
        }
    }
}

extern "C" void kernel_launch(void* const* d_in, const int* in_sizes, int n_in,
                              void* d_out, int out_size) {
    const float* logits = (const float*)d_in[0];
    const float* iou    = (const float*)d_in[1];
    float* dout = (float*)d_out;

    // One-time side-stream/event setup (first call = correctness run, outside
    // graph capture; no device memory involved).
    static cudaStream_t s2 = nullptr;
    static cudaEvent_t ev_fork = nullptr;
    static cudaEvent_t ev_join = nullptr;
    if (s2 == nullptr) {
        cudaStreamCreateWithFlags(&s2, cudaStreamNonBlocking);
        cudaEventCreateWithFlags(&ev_fork, cudaEventDisableTiming);
        cudaEventCreateWithFlags(&ev_join, cudaEventDisableTiming);
    }

    // Fork: zero-fill of invalid-iou mask regions runs concurrently with the
    // stats read pass (overlaps write BW with read BW).
    cudaEventRecord(ev_fork, 0);
    cudaStreamWaitEvent(s2, ev_fork, 0);
    zfill_kernel<<<dim3(8, NM), 256, 0, s2>>>(iou, dout);
    cudaEventRecord(ev_join, s2);

    // Main branch.
    stats_kernel<<<NPART, 256>>>(logits);
    nms_kernel<<<1, 1024>>>(iou, dout, (long long)out_size);

    // Join before the post-NMS output writes.
    cudaStreamWaitEvent(0, ev_join, 0);
    output_kernel<<<dim3(8, NM), 256>>>(logits, iou, dout);
}

// round 17
// speedup vs baseline: 1.0519x; 1.0519x over previous
#include <cuda_runtime.h>
#include <math.h>

#define NM 1024
#define H 256
#define W 256
#define HW (H * W)
#define TOTAL ((size_t)NM * HW)
#define CHUNKS 4
#define NPART (NM * CHUNKS)

#define PRED_IOU_THRESH 0.88f
#define STABILITY_THRESH 0.95f
#define BOX_NMS_THRESH 0.7f

// Per-mask / per-partial scratch (allocation-free: __device__ globals)
__device__ int4   g_pA[NPART];   // hi, lo, minr, maxr
__device__ int2   g_pB[NPART];   // minc, maxc
__device__ float4 g_boxes[NM];   // xyxy inclusive, zeros if empty
__device__ float  g_gated[NM];   // iou_pred if kept else 0
__device__ int    g_klist[NM];   // compacted kept-mask ids
__device__ int    g_nkept;       // count (rewritten every launch)

// ---------------------------------------------------------------------------
// Pass 1: partial stats, READ-ONLY (82% DRAM — at ceiling, frozen).
// ---------------------------------------------------------------------------
__global__ void __launch_bounds__(256) stats_kernel(const float* __restrict__ logits) {
    const int blk = blockIdx.x;
    const int m = blk >> 2;
    const int chunk = blk & 3;
    const int tid = threadIdx.x;
    const float4* base = reinterpret_cast<const float4*>(logits)
                       + (size_t)m * (HW / 4) + chunk * 4096;

    int hi = 0, lo = 0;
    unsigned rowbits = 0;
    float cm0 = -1e30f, cm1 = -1e30f, cm2 = -1e30f, cm3 = -1e30f;

#pragma unroll
    for (int it = 0; it < 16; ++it) {
        float4 v = __ldcs(&base[it * 256 + tid]);
        hi += (v.x > 1.0f) + (v.y > 1.0f) + (v.z > 1.0f) + (v.w > 1.0f);
        lo += (v.x > -1.0f) + (v.y > -1.0f) + (v.z > -1.0f) + (v.w > -1.0f);
        cm0 = fmaxf(cm0, v.x);
        cm1 = fmaxf(cm1, v.y);
        cm2 = fmaxf(cm2, v.z);
        cm3 = fmaxf(cm3, v.w);
        float mx = fmaxf(fmaxf(v.x, v.y), fmaxf(v.z, v.w));
        if (mx > 0.0f) rowbits |= (1u << it);
    }

    const int col0 = (tid * 4) & 255;
    int minc = W, maxc = -1;
    if (cm0 > 0.0f) { minc = col0;                 maxc = col0;     }
    if (cm1 > 0.0f) { minc = min(minc, col0 + 1);  maxc = col0 + 1; }
    if (cm2 > 0.0f) { minc = min(minc, col0 + 2);  maxc = col0 + 2; }
    if (cm3 > 0.0f) { minc = min(minc, col0 + 3);  maxc = col0 + 3; }
    int minr = H, maxr = -1;
    if (rowbits) {
        int rb = chunk * 64 + (tid >> 6);
        minr = rb + 4 * (__ffs(rowbits) - 1);
        maxr = rb + 4 * (31 - __clz(rowbits));
    }

#pragma unroll
    for (int off = 16; off > 0; off >>= 1) {
        hi   += __shfl_down_sync(0xffffffffu, hi, off);
        lo   += __shfl_down_sync(0xffffffffu, lo, off);
        minr = min(minr, __shfl_down_sync(0xffffffffu, minr, off));
        maxr = max(maxr, __shfl_down_sync(0xffffffffu, maxr, off));
        minc = min(minc, __shfl_down_sync(0xffffffffu, minc, off));
        maxc = max(maxc, __shfl_down_sync(0xffffffffu, maxc, off));
    }

    __shared__ int sh[8][6];
    int warp = tid >> 5;
    if ((tid & 31) == 0) {
        sh[warp][0] = hi;  sh[warp][1] = lo;
        sh[warp][2] = minr; sh[warp][3] = maxr;
        sh[warp][4] = minc; sh[warp][5] = maxc;
    }
    __syncthreads();
    if (tid == 0) {
#pragma unroll
        for (int wq = 1; wq < 8; ++wq) {
            hi += sh[wq][0]; lo += sh[wq][1];
            minr = min(minr, sh[wq][2]); maxr = max(maxr, sh[wq][3]);
            minc = min(minc, sh[wq][4]); maxc = max(maxc, sh[wq][5]);
        }
        g_pA[blk] = make_int4(hi, lo, minr, maxr);
        g_pB[blk] = make_int2(minc, maxc);
    }
}

// ---------------------------------------------------------------------------
// IoU helper (exact match of reference, incl. 1e-6 clamp)
// ---------------------------------------------------------------------------
__device__ __forceinline__ float box_iou(float4 a, float4 b, float area_b) {
    float x0 = fmaxf(a.x, b.x);
    float y0 = fmaxf(a.y, b.y);
    float x1 = fminf(a.z, b.z);
    float y1 = fminf(a.w, b.w);
    float inter = fmaxf(x1 - x0, 0.0f) * fmaxf(y1 - y0, 0.0f);
    float area_a = fmaxf(a.z - a.x, 0.0f) * fmaxf(a.w - a.y, 0.0f);
    return inter / fmaxf(area_a + area_b - inter, 1e-6f);
}

// ---------------------------------------------------------------------------
// NMS: single block, 1024 threads. Merge partials -> validity/box.
// Fast path (V<=256): ballot compaction, 256-wide bitonic, adjacency bitmask
// + single-thread sweep. Fallback (V>256): exact full sort + greedy.
// Also builds the compacted kept-mask worklist for the output kernel.
// ---------------------------------------------------------------------------
__global__ void __launch_bounds__(1024) nms_kernel(const float* __restrict__ iou_preds,
                                                   float* __restrict__ dout,
                                                   long long out_size) {
    __shared__ float    css[256];
    __shared__ int      cidx[256];
    __shared__ float4   cbox[256];
    __shared__ unsigned adj[256][8];
    __shared__ unsigned removed_sh[8];
    __shared__ int      woff[33];
    __shared__ unsigned char keep_orig[NM];
    __shared__ int      s_nkept;

    const int t = threadIdx.x;
    const int lane = t & 31;
    const int warp = t >> 5;

    int hi = 0, lo = 0, minr = H, maxr = -1, minc = W, maxc = -1;
#pragma unroll
    for (int c = 0; c < CHUNKS; ++c) {
        int4 a = g_pA[t * CHUNKS + c];
        int2 b = g_pB[t * CHUNKS + c];
        hi += a.x; lo += a.y;
        minr = min(minr, a.z); maxr = max(maxr, a.w);
        minc = min(minc, b.x); maxc = max(maxc, b.y);
    }
    float stability = (float)hi / fmaxf((float)lo, 1.0f);
    float iou_p = iou_preds[t];
    bool valid = (iou_p > PRED_IOU_THRESH) && (stability >= STABILITY_THRESH);
    float4 box = (maxr < 0) ? make_float4(0.f, 0.f, 0.f, 0.f)
                            : make_float4((float)minc, (float)minr, (float)maxc, (float)maxr);
    g_boxes[t] = box;
    keep_orig[t] = 0;
    if (t == 0) s_nkept = 0;

    unsigned wmask = __ballot_sync(0xffffffffu, valid);
    if (lane == 0) woff[warp] = __popc(wmask);
    __syncthreads();
    if (t < 32) {
        int v = woff[t];
        int acc = v;
#pragma unroll
        for (int off = 1; off < 32; off <<= 1) {
            int n = __shfl_up_sync(0xffffffffu, acc, off);
            if (t >= off) acc += n;
        }
        woff[t] = acc - v;
        if (t == 31) woff[32] = acc;
    }
    __syncthreads();
    const int V = woff[32];
    if (valid && V <= 256) {
        int mypos = woff[warp] + __popc(wmask & ((1u << lane) - 1u));
        css[mypos] = iou_p;
        cidx[mypos] = t;
        cbox[mypos] = box;
    }

    if (V <= 256) {
        if (t >= V && t < 256) {
            css[t] = -INFINITY;
            cidx[t] = NM + t;
            cbox[t] = make_float4(0.f, 0.f, 0.f, 0.f);
        }
        reinterpret_cast<unsigned*>(adj)[t] = 0;
        reinterpret_cast<unsigned*>(adj)[t + 1024] = 0;
        __syncthreads();

        for (int k = 2; k <= 256; k <<= 1) {
            for (int j = k >> 1; j > 0; j >>= 1) {
                if (t < 256) {
                    int ixj = t ^ j;
                    if (ixj > t) {
                        float sa = css[t], sb_ = css[ixj];
                        int   ia = cidx[t], ib = cidx[ixj];
                        bool less = (sa > sb_) || (sa == sb_ && ia < ib);
                        bool dir = ((t & k) == 0);
                        if (less != dir) {
                            css[t] = sb_; css[ixj] = sa;
                            cidx[t] = ib; cidx[ixj] = ia;
                            float4 ba = cbox[t];
                            cbox[t] = cbox[ixj]; cbox[ixj] = ba;
                        }
                    }
                }
                __syncthreads();
            }
        }

        if (t < V) {
            float4 bt = cbox[t];
            float area_t = fmaxf(bt.z - bt.x, 0.0f) * fmaxf(bt.w - bt.y, 0.0f);
            for (int i = 0; i < t; ++i) {
                if (box_iou(cbox[i], bt, area_t) > BOX_NMS_THRESH)
                    atomicOr(&adj[i][t >> 5], 1u << (t & 31));
            }
        }
        __syncthreads();
        if (t == 0) {
            unsigned removed[8] = {0,0,0,0,0,0,0,0};
            int nw = (V + 31) >> 5;
            for (int i = 0; i < V; ++i) {
                if (!((removed[i >> 5] >> (i & 31)) & 1u)) {
                    for (int w = 0; w < nw; ++w) removed[w] |= adj[i][w];
                }
            }
#pragma unroll
            for (int w = 0; w < 8; ++w) removed_sh[w] = removed[w];
        }
        __syncthreads();
        if (t < V) {
            bool kept = !((removed_sh[t >> 5] >> (t & 31)) & 1u);
            if (kept) keep_orig[cidx[t]] = 1;
        }
        __syncthreads();
    } else {
        __shared__ float  ss[NM];
        __shared__ int    si[NM];
        __shared__ float4 sbx[NM];
        __shared__ int    sk[NM];
        ss[t] = valid ? iou_p : -INFINITY;
        si[t] = t;
        __syncthreads();
        for (int k = 2; k <= NM; k <<= 1) {
            for (int j = k >> 1; j > 0; j >>= 1) {
                int ixj = t ^ j;
                if (ixj > t) {
                    float sa = ss[t], sb_ = ss[ixj];
                    int   ia = si[t], ib = si[ixj];
                    bool less = (sa > sb_) || (sa == sb_ && ia < ib);
                    bool dir = ((t & k) == 0);
                    if (less != dir) {
                        ss[t] = sb_; ss[ixj] = sa;
                        si[t] = ib;  si[ixj] = ia;
                    }
                }
                __syncthreads();
            }
        }
        sbx[t] = g_boxes[si[t]];
        sk[t] = (ss[t] > -INFINITY) ? 1 : 0;
        __syncthreads();
        float4 bt = sbx[t];
        float area_t = fmaxf(bt.z - bt.x, 0.0f) * fmaxf(bt.w - bt.y, 0.0f);
        for (int i = 0; i < V; ++i) {
            if (sk[i]) {
                float iou = box_iou(sbx[i], bt, area_t);
                if (t > i && iou > BOX_NMS_THRESH) sk[t] = 0;
            }
            __syncthreads();
        }
        if (sk[t]) keep_orig[si[t]] = 1;
        __syncthreads();
    }

    // per-mask results in original order + compacted kept worklist
    int kept = keep_orig[t];
    g_gated[t] = kept ? iou_p : 0.0f;
    if (kept) {
        int pos = atomicAdd(&s_nkept, 1);
        g_klist[pos] = t;
    }
    if (out_size >= (long long)(TOTAL + NM)) {
        dout[TOTAL + t] = kept ? 1.0f : 0.0f;
    }
    if (out_size >= (long long)(TOTAL + NM + 4 * NM)) {
        float4* boxout = reinterpret_cast<float4*>(dout + TOTAL + NM);
        boxout[t] = g_boxes[t];
    }
    __syncthreads();
    if (t == 0) g_nkept = s_nkept;
}

// ---------------------------------------------------------------------------
// Post-NMS output: persistent 1024-block grid looping over the compacted
// kept-mask worklist (8 x 32KB chunks per kept mask). No dead blocks.
// Everything else is already zeroed by the memset node.
// ---------------------------------------------------------------------------
__global__ void __launch_bounds__(256) output_kernel(const float* __restrict__ logits,
                                                     float* __restrict__ dout) {
    const int nwork = g_nkept * 8;
    for (int w = blockIdx.x; w < nwork; w += gridDim.x) {
        const int m = g_klist[w >> 3];
        const int chunk = w & 7;
        const float g = g_gated[m];
        const size_t base4 = (size_t)m * (HW / 4) + chunk * 2048;
        const float4* in = reinterpret_cast<const float4*>(logits) + base4;
        float4* o = reinterpret_cast<float4*>(dout) + base4;
#pragma unroll
        for (int it = 0; it < 8; ++it) {
            float4 v = __ldcs(&in[it * 256 + threadIdx.x]);
            float4 r;
            r.x = g / (1.0f + __expf(-v.x));
            r.y = g / (1.0f + __expf(-v.y));
            r.z = g / (1.0f + __expf(-v.z));
            r.w = g / (1.0f + __expf(-v.w));
            __stcs(&o[it * 256 + threadIdx.x], r);
        }
    }
}

extern "C" void kernel_launch(void* const* d_in, const int* in_sizes, int n_in,
                              void* d_out, int out_size) {
    const float* logits = (const float*)d_in[0];
    const float* iou    = (const float*)d_in[1];
    float* dout = (float*)d_out;

    // One-time side-stream/event setup (first call = correctness run, outside
    // graph capture; no device memory involved).
    static cudaStream_t s2 = nullptr;
    static cudaEvent_t ev_fork = nullptr;
    static cudaEvent_t ev_join = nullptr;
    if (s2 == nullptr) {
        cudaStreamCreateWithFlags(&s2, cudaStreamNonBlocking);
        cudaEventCreateWithFlags(&ev_fork, cudaEventDisableTiming);
        cudaEventCreateWithFlags(&ev_join, cudaEventDisableTiming);
    }

    // Fork: driver memset of the whole [N,H,W] region runs concurrently with
    // the stats read pass + NMS.
    cudaEventRecord(ev_fork, 0);
    cudaStreamWaitEvent(s2, ev_fork, 0);
    cudaMemsetAsync(dout, 0, TOTAL * sizeof(float), s2);
    cudaEventRecord(ev_join, s2);

    // Main branch.
    stats_kernel<<<NPART, 256>>>(logits);
    nms_kernel<<<1, 1024>>>(iou, dout, (long long)out_size);

    // Join: kept-mask writes must land after the memset.
    cudaStreamWaitEvent(0, ev_join, 0);
    output_kernel<<<1024, 256>>>(logits, dout);
}